// round 15
// baseline (speedup 1.0000x reference)
#include <cuda_runtime.h>
#include <cuda_fp16.h>

#define H_IMG 1080
#define W_IMG 1920
#define GY 16
#define GX 16
#define GW 8
#define NPIX (H_IMG * W_IMG)

#define BX 384                      // threads per block
#define PXB 256                     // pixels per block (2 elements/thread)
#define NC 4                        // x-cell columns (incl. +1 margin)
#define NCELL (NC * GW)             // 32 cells, 96 slab entries

#define SX (15.0f / 1919.0f)
#define SY (15.0f / 1079.0f)

__device__ __forceinline__ unsigned f2h2(float a, float b) {
    __half2 h = __floats2half2_rn(a, b);
    return *reinterpret_cast<unsigned*>(&h);
}
__device__ __forceinline__ float2 h2f(unsigned u) {
    __half2 h;
    *reinterpret_cast<unsigned*>(&h) = u;
    return __half22float2(h);
}

__global__ __launch_bounds__(BX) void bilateral_grid_kernel(
    const float* __restrict__ rgb,
    const float* __restrict__ grids,
    const int*   __restrict__ idxp,
    float*       __restrict__ out)
{
    __shared__ __align__(16) uint4 slabh[NCELL * 3];   // 1536B

    const int tid   = threadIdx.x;
    const int row   = blockIdx.y;
    const int xpix0 = blockIdx.x * PXB;
    const int xbase = (int)((float)xpix0 * SX);

    const int q0 = tid / 3;
    const int c  = tid - 3 * q0;
    const int q1 = q0 + 128;
    const bool has1 = (xpix0 + q1 < W_IMG);

    // ---- rgb prefetch ----
    const int n0 = row * W_IMG + xpix0 + q0;
    float r0 = __ldcs(rgb + n0);
    float g0 = __ldcs(rgb + NPIX + n0);
    float b0 = __ldcs(rgb + 2 * NPIX + n0);
    float r1 = 0.f, g1 = 0.f, b1 = 0.f;
    if (has1) {
        r1 = __ldcs(rgb + n0 + 128);
        g1 = __ldcs(rgb + NPIX + n0 + 128);
        b1 = __ldcs(rgb + 2 * NPIX + n0 + 128);
    }

    if (tid < NCELL * 3) {
        // ---- slab build: y-lerp + z-delta, packed fp16. 96 threads ----
        const float* grid = grids + (size_t)idxp[0] * (GY * GX * GW * 12);
        float gyv = (float)row * SY;
        float fy  = floorf(gyv);
        float wy  = gyv - fy;
        int y0 = min((int)fy, GY - 1);
        int y1 = min(y0 + 1, GY - 1);
        float wy0 = 1.0f - wy, wy1 = wy;

        int cell = tid / 3;
        int c4   = tid - cell * 3;
        int xq   = cell / GW;
        int zq   = cell - xq * GW;
        int zq1  = min(zq + 1, GW - 1);
        int xc   = min(xbase + xq, GX - 1);

        float4 a0 = __ldg(reinterpret_cast<const float4*>(
            grid + ((size_t)(y0 * GX + xc) * GW + zq)  * 12) + c4);
        float4 a1 = __ldg(reinterpret_cast<const float4*>(
            grid + ((size_t)(y1 * GX + xc) * GW + zq)  * 12) + c4);
        float4 bb0 = __ldg(reinterpret_cast<const float4*>(
            grid + ((size_t)(y0 * GX + xc) * GW + zq1) * 12) + c4);
        float4 bb1 = __ldg(reinterpret_cast<const float4*>(
            grid + ((size_t)(y1 * GX + xc) * GW + zq1) * 12) + c4);

        float4 v, nx;
        v.x  = wy0 * a0.x  + wy1 * a1.x;   v.y  = wy0 * a0.y  + wy1 * a1.y;
        v.z  = wy0 * a0.z  + wy1 * a1.z;   v.w  = wy0 * a0.w  + wy1 * a1.w;
        nx.x = wy0 * bb0.x + wy1 * bb1.x;  nx.y = wy0 * bb0.y + wy1 * bb1.y;
        nx.z = wy0 * bb0.z + wy1 * bb1.z;  nx.w = wy0 * bb0.w + wy1 * bb1.w;

        uint4 pk;
        pk.x = f2h2(v.x, v.y);
        pk.y = f2h2(v.z, v.w);
        pk.z = f2h2(nx.x - v.x, nx.y - v.y);
        pk.w = f2h2(nx.z - v.z, nx.w - v.w);
        slabh[tid] = pk;
    }
    __syncthreads();

    const size_t base3 = (size_t)(row * W_IMG + xpix0) * 3;
    float4* aff = reinterpret_cast<float4*>(out) + base3;
    float*  res = out + (size_t)12 * NPIX + base3;

    #define DO_ELEM(qq, rv, gv, bv, off)                                       \
    {                                                                          \
        float gray = 0.299f * (rv) + 0.587f * (gv) + 0.114f * (bv);            \
        float gz = __saturatef(gray) * 7.0f;                                   \
        float fz = floorf(gz);                                                 \
        float wz = gz - fz;                                                    \
        int z0 = (int)fz;                                                      \
                                                                               \
        /* x math in registers */                                              \
        float gxv = (float)(xpix0 + (qq)) * SX;                                \
        float fx  = floorf(gxv);                                               \
        float wx  = gxv - fx;                                                  \
        int xc0 = min((int)fx, GX - 1);                                        \
        int ia = (xc0 - xbase) * (GW * 3) + z0 * 3 + c;                        \
                                                                               \
        uint4 ua = slabh[ia];                                                  \
        uint4 ub = slabh[ia + GW * 3];                                         \
                                                                               \
        /* z-lerp in half2: t = val + wz*dz */                                 \
        __half2 wz2 = __float2half2_rn(wz);                                    \
        __half2 ta0 = __hfma2(wz2, *(__half2*)&ua.z, *(__half2*)&ua.x);        \
        __half2 ta1 = __hfma2(wz2, *(__half2*)&ua.w, *(__half2*)&ua.y);        \
        __half2 tb0 = __hfma2(wz2, *(__half2*)&ub.z, *(__half2*)&ub.x);        \
        __half2 tb1 = __hfma2(wz2, *(__half2*)&ub.w, *(__half2*)&ub.y);        \
                                                                               \
        float2 fa0 = __half22float2(ta0), fa1 = __half22float2(ta1);           \
        float2 fb0 = __half22float2(tb0), fb1 = __half22float2(tb1);           \
                                                                               \
        float w0 = 1.0f - wx;                                                  \
        float4 a4;                                                             \
        a4.x = fmaf(wx, fb0.x, w0 * fa0.x);                                    \
        a4.y = fmaf(wx, fb0.y, w0 * fa0.y);                                    \
        a4.z = fmaf(wx, fb1.x, w0 * fa1.x);                                    \
        a4.w = fmaf(wx, fb1.y, w0 * fa1.y);                                    \
                                                                               \
        __stcs(aff + tid + (off), a4);                                         \
        __stcs(res + tid + (off),                                              \
               fmaf(a4.x, (rv), fmaf(a4.y, (gv), fmaf(a4.z, (bv), a4.w))));    \
    }

    DO_ELEM(q0, r0, g0, b0, 0)
    if (has1) DO_ELEM(q1, r1, g1, b1, BX)
    #undef DO_ELEM
}

extern "C" void kernel_launch(void* const* d_in, const int* in_sizes, int n_in,
                              void* d_out, int out_size) {
    const float* rgb   = (const float*)d_in[0];
    const float* grids = (const float*)d_in[1];
    const int*   idx   = (const int*)d_in[2];
    float* out = (float*)d_out;

    dim3 grid((W_IMG + PXB - 1) / PXB, H_IMG);   // 8 x 1080
    bilateral_grid_kernel<<<grid, BX>>>(rgb, grids, idx, out);
}

// round 16
// speedup vs baseline: 1.1067x; 1.1067x over previous
#include <cuda_runtime.h>
#include <cuda_fp16.h>

#define H_IMG 1080
#define W_IMG 1920
#define GY 16
#define GX 16
#define GW 8
#define NPIX (H_IMG * W_IMG)

#define BX 384                      // threads per block
#define PXB 256                     // pixels per block (2 elements/thread)
#define NC 4                        // x-cell columns (incl. +1 margin)
#define NCELL (NC * GW)             // 32 cells, 96 slab entries

#define SX (15.0f / 1919.0f)
#define SY (15.0f / 1079.0f)

__device__ __forceinline__ unsigned f2h2(float a, float b) {
    __half2 h = __floats2half2_rn(a, b);
    return *reinterpret_cast<unsigned*>(&h);
}

__global__ __launch_bounds__(BX) void bilateral_grid_kernel(
    const float* __restrict__ rgb,
    const float* __restrict__ grids,
    const int*   __restrict__ idxp,
    float*       __restrict__ out)
{
    __shared__ __align__(16) uint4  slabh[NCELL * 3];   // 1536B
    __shared__ __align__(8)  float2 xtab[128];          // 1KB: {wx, o0 bits}, q=0..127

    const int tid   = threadIdx.x;
    const int row   = blockIdx.y;
    const int xpix0 = blockIdx.x * PXB;
    const int xbase = (int)((float)xpix0 * SX);

    const int q0 = tid / 3;
    const int c  = tid - 3 * q0;
    const int q1 = q0 + 128;
    const bool has1 = (xpix0 + q1 < W_IMG);

    // NOTE: xtab holds only q=0..127 entries? No — need q up to 255.
    // Layout: xtab covers 256 pixels in two banks of 128 (see build below).
    // We size it 256 via a second array section appended right after.
    // (kept as one 256-entry array)
    // -- replaced below --

    // ---- rgb prefetch ----
    const int n0 = row * W_IMG + xpix0 + q0;
    float r0 = __ldcs(rgb + n0);
    float g0 = __ldcs(rgb + NPIX + n0);
    float b0 = __ldcs(rgb + 2 * NPIX + n0);
    float r1 = 0.f, g1 = 0.f, b1 = 0.f;
    if (has1) {
        r1 = __ldcs(rgb + n0 + 128);
        g1 = __ldcs(rgb + NPIX + n0 + 128);
        b1 = __ldcs(rgb + 2 * NPIX + n0 + 128);
    }

    if (tid < NCELL * 3) {
        // ---- slab build: y-lerp + z-delta, packed fp16. 96 threads ----
        const float* grid = grids + (size_t)idxp[0] * (GY * GX * GW * 12);
        float gyv = (float)row * SY;
        float fy  = floorf(gyv);
        float wy  = gyv - fy;
        int y0 = min((int)fy, GY - 1);
        int y1 = min(y0 + 1, GY - 1);
        float wy0 = 1.0f - wy, wy1 = wy;

        int cell = tid / 3;
        int c4   = tid - cell * 3;
        int xq   = cell / GW;
        int zq   = cell - xq * GW;
        int zq1  = min(zq + 1, GW - 1);
        int xc   = min(xbase + xq, GX - 1);

        float4 a0 = __ldg(reinterpret_cast<const float4*>(
            grid + ((size_t)(y0 * GX + xc) * GW + zq)  * 12) + c4);
        float4 a1 = __ldg(reinterpret_cast<const float4*>(
            grid + ((size_t)(y1 * GX + xc) * GW + zq)  * 12) + c4);
        float4 bb0 = __ldg(reinterpret_cast<const float4*>(
            grid + ((size_t)(y0 * GX + xc) * GW + zq1) * 12) + c4);
        float4 bb1 = __ldg(reinterpret_cast<const float4*>(
            grid + ((size_t)(y1 * GX + xc) * GW + zq1) * 12) + c4);

        float4 v, nx;
        v.x  = wy0 * a0.x  + wy1 * a1.x;   v.y  = wy0 * a0.y  + wy1 * a1.y;
        v.z  = wy0 * a0.z  + wy1 * a1.z;   v.w  = wy0 * a0.w  + wy1 * a1.w;
        nx.x = wy0 * bb0.x + wy1 * bb1.x;  nx.y = wy0 * bb0.y + wy1 * bb1.y;
        nx.z = wy0 * bb0.z + wy1 * bb1.z;  nx.w = wy0 * bb0.w + wy1 * bb1.w;

        uint4 pk;
        pk.x = f2h2(v.x, v.y);
        pk.y = f2h2(v.z, v.w);
        pk.z = f2h2(nx.x - v.x, nx.y - v.y);
        pk.w = f2h2(nx.z - v.z, nx.w - v.w);
        slabh[tid] = pk;
    }

    // ---- x-table build for q=0..255: threads 128..383 ----
    __shared__ __align__(8) float2 xtab2[128];   // q=128..255
    if (tid >= 128) {
        int qq = tid - 128;
        int x  = xpix0 + qq;
        float gxv = (float)min(x, W_IMG - 1) * SX;
        float fx  = floorf(gxv);
        float wx  = gxv - fx;
        int xc0 = min((int)fx, GX - 1);
        int o0 = (xc0 - xbase) * (GW * 3);
        if (qq < 128) xtab[qq] = make_float2(wx, __int_as_float(o0));
        else          xtab2[qq - 128] = make_float2(wx, __int_as_float(o0));
    }
    __syncthreads();

    const size_t base3 = (size_t)(row * W_IMG + xpix0) * 3;
    float4* aff = reinterpret_cast<float4*>(out) + base3;
    float*  res = out + (size_t)12 * NPIX + base3;

    #define DO_ELEM(xe, rv, gv, bv, off)                                       \
    {                                                                          \
        float gray = 0.299f * (rv) + 0.587f * (gv) + 0.114f * (bv);            \
        float gz = __saturatef(gray) * 7.0f;                                   \
        float fz = floorf(gz);                                                 \
        float wz = gz - fz;                                                    \
        int z0 = (int)fz;                                                      \
                                                                               \
        float wx  = (xe).x;                                                    \
        int ia = __float_as_int((xe).y) + z0 * 3 + c;                          \
        uint4 ua = slabh[ia];                                                  \
        uint4 ub = slabh[ia + GW * 3];                                         \
                                                                               \
        __half2 wz2 = __float2half2_rn(wz);                                    \
        __half2 ta0 = __hfma2(wz2, *(__half2*)&ua.z, *(__half2*)&ua.x);        \
        __half2 ta1 = __hfma2(wz2, *(__half2*)&ua.w, *(__half2*)&ua.y);        \
        __half2 tb0 = __hfma2(wz2, *(__half2*)&ub.z, *(__half2*)&ub.x);        \
        __half2 tb1 = __hfma2(wz2, *(__half2*)&ub.w, *(__half2*)&ub.y);        \
                                                                               \
        float2 fa0 = __half22float2(ta0), fa1 = __half22float2(ta1);           \
        float2 fb0 = __half22float2(tb0), fb1 = __half22float2(tb1);           \
                                                                               \
        float w0 = 1.0f - wx;                                                  \
        float4 a4;                                                             \
        a4.x = fmaf(wx, fb0.x, w0 * fa0.x);                                    \
        a4.y = fmaf(wx, fb0.y, w0 * fa0.y);                                    \
        a4.z = fmaf(wx, fb1.x, w0 * fa1.x);                                    \
        a4.w = fmaf(wx, fb1.y, w0 * fa1.y);                                    \
                                                                               \
        __stcs(aff + tid + (off), a4);                                         \
        __stcs(res + tid + (off),                                              \
               fmaf(a4.x, (rv), fmaf(a4.y, (gv), fmaf(a4.z, (bv), a4.w))));    \
    }

    {
        float2 xe0 = xtab[q0];
        DO_ELEM(xe0, r0, g0, b0, 0)
    }
    if (has1) {
        float2 xe1 = xtab2[q1 - 128];
        DO_ELEM(xe1, r1, g1, b1, BX)
    }
    #undef DO_ELEM
}

extern "C" void kernel_launch(void* const* d_in, const int* in_sizes, int n_in,
                              void* d_out, int out_size) {
    const float* rgb   = (const float*)d_in[0];
    const float* grids = (const float*)d_in[1];
    const int*   idx   = (const int*)d_in[2];
    float* out = (float*)d_out;

    dim3 grid((W_IMG + PXB - 1) / PXB, H_IMG);   // 8 x 1080
    bilateral_grid_kernel<<<grid, BX>>>(rgb, grids, idx, out);
}